// round 11
// baseline (speedup 1.0000x reference)
#include <cuda_runtime.h>
#include <cstdint>

// Problem dims
#define Bn   256
#define Sn   512
#define Cn   256
#define Vn   32
#define NLn  7
#define Mn   (Bn*Sn)
#define EPSn 1e-5f

// Scratch
__device__ float g_h[(size_t)Mn*Cn];
__device__ float g_a[(size_t)Mn*Cn];
__device__ float g_t[(size_t)Mn*Cn];
__device__ float g_lat[Bn*Cn];
__device__ float g_wt[35*65536];        // transposed weights [35][N=256][K=256]
__device__ float2 g_acc[2*Mn];          // per-row (sum,sumsq) partials of h, per n-half

// ---------------------------------------------------------------------------
__device__ __forceinline__ uint32_t smem_u32(const void* p) {
    uint32_t a;
    asm("{ .reg .u64 t; cvta.to.shared.u64 t, %1; cvt.u32.u64 %0, t; }"
        : "=r"(a) : "l"(p));
    return a;
}
#define CP16(dst, src, sz) \
    asm volatile("cp.async.cg.shared.global [%0], [%1], 16, %2;" \
        :: "r"(dst), "l"(src), "r"(sz))
#define CPCOMMIT() asm volatile("cp.async.commit_group;")
#define CPWAIT(n)  asm volatile("cp.async.wait_group %0;" :: "n"(n))

__device__ __forceinline__ void ldsm4(uint32_t* r, uint32_t addr) {
    asm volatile("ldmatrix.sync.aligned.m8n8.x4.shared.b16 {%0,%1,%2,%3}, [%4];"
        : "=r"(r[0]), "=r"(r[1]), "=r"(r[2]), "=r"(r[3]) : "r"(addr));
}

__device__ __forceinline__ void mma_tf32(float* c, const uint32_t* a, const uint32_t* b) {
    asm volatile(
        "mma.sync.aligned.m16n8k8.row.col.f32.tf32.tf32.f32 "
        "{%0,%1,%2,%3}, {%4,%5,%6,%7}, {%8,%9}, {%0,%1,%2,%3};"
        : "+f"(c[0]), "+f"(c[1]), "+f"(c[2]), "+f"(c[3])
        : "r"(a[0]), "r"(a[1]), "r"(a[2]), "r"(a[3]), "r"(b[0]), "r"(b[1]));
}

// ---------------------------------------------------------------------------
// Weight transpose: g_wt[mat][n][k] = W[k][n]
__global__ __launch_bounds__(256) void transpose_w_kernel(
    const float* __restrict__ w1, const float* __restrict__ wd,
    const float* __restrict__ we, const float* __restrict__ wg)
{
    __shared__ float t[32][33];
    int mat = blockIdx.z;
    int layer = mat / 5, wh = mat % 5;
    const size_t CC = 65536;
    const float* src;
    if      (wh == 0) src = w1 + (size_t)layer*CC;
    else if (wh == 1) src = wd + (size_t)layer*2*CC;
    else if (wh == 2) src = wd + (size_t)layer*2*CC + CC;
    else if (wh == 3) src = we + (size_t)layer*CC;
    else              src = wg + (size_t)layer*CC;
    int tx = threadIdx.x & 31, ty = threadIdx.x >> 5;
    int k0 = blockIdx.x*32, n0 = blockIdx.y*32;
    #pragma unroll
    for (int j = 0; j < 32; j += 8)
        t[ty+j][tx] = src[(size_t)(k0+ty+j)*256 + n0 + tx];
    __syncthreads();
    float* dst = g_wt + (size_t)mat*CC;
    #pragma unroll
    for (int j = 0; j < 32; j += 8)
        dst[(size_t)(n0+ty+j)*256 + k0 + tx] = t[tx][ty+j];
}

// ---------------------------------------------------------------------------
// GEMM with fused LayerNorm+lrelu epilogue, ldmatrix fragment loads.
// Tile 64x256, BK=32, 8 warps (2 m x 4 n), warp tile 32x64.
// LNA=true: A-operand is h with ln1 applied during staging (stats from g_acc).
template<int KITERS, bool CONV, bool LNA>
__global__ __launch_bounds__(256, 2) void gemm_ln_kernel(
    const float* __restrict__ A,
    const float* __restrict__ W0t, const float* __restrict__ W1t,
    const float* __restrict__ bias,
    const float* __restrict__ gamma, const float* __restrict__ beta,
    float* __restrict__ out, int d,
    const float2* __restrict__ accH,
    const float* __restrict__ ag, const float* __restrict__ ab)
{
    extern __shared__ __align__(128) char smem[];
    const uint32_t STAGE = 40960u;   // A 8KB + B 32KB
    uint32_t sb = smem_u32(smem);

    int tid = threadIdx.x;
    int wid = tid >> 5, lane = tid & 31;
    int g = lane >> 2, tq = lane & 3;
    int warp_m = wid >> 2, warp_n = wid & 3;
    int m_base = warp_m * 32, n_base = warp_n * 64;
    int row0 = blockIdx.x * 64;

    float acc[2][8][4];
    #pragma unroll
    for (int i = 0; i < 2; i++)
        #pragma unroll
        for (int j = 0; j < 8; j++)
            #pragma unroll
            for (int q = 0; q < 4; q++) acc[i][j][q] = 0.f;

    // ldmatrix lane constants
    int lj = lane >> 3, lr = lane & 7;
    int j1 = lj & 1, j2 = lj >> 1;
    uint32_t aLM[2], bLM[4];
    #pragma unroll
    for (int mi = 0; mi < 2; mi++) {
        int rl = m_base + mi*16 + j1*8 + lr;
        aLM[mi] = (uint32_t)rl*128 + (((uint32_t)(j2 ^ lr))<<4);
    }
    #pragma unroll
    for (int nip = 0; nip < 4; nip++) {
        int rl = n_base + nip*16 + j2*8 + lr;
        bLM[nip] = (uint32_t)rl*128 + (((uint32_t)(j1 ^ lr))<<4);
    }

    // per-thread A-staging row constants
    int a_row0 = tid >> 3;          // rows a_row0 and a_row0+32
    int a_ch   = tid & 7;
    float mu_[2], rs_[2];
    if (LNA) {
        #pragma unroll
        for (int i = 0; i < 2; i++) {
            int gm = row0 + a_row0 + 32*i;
            float2 p0 = accH[gm];
            float2 p1 = accH[Mn + gm];
            float s = p0.x + p1.x, q = p0.y + p1.y;
            float m = s * (1.0f/Cn);
            mu_[i] = m;
            rs_[i] = rsqrtf(q * (1.0f/Cn) - m*m + EPSn);
        }
    }

    // B staging (cp.async)
    auto stageB = [&](int buf, int it) {
        const float* W = (CONV && it >= 8) ? W1t : W0t;
        int kcol = (it & 7) * 32;
        uint32_t base = sb + buf*STAGE;
        #pragma unroll
        for (int i = 0; i < 8; i++) {
            int cidx = tid + 256*i;
            int row = cidx >> 3, ch = cidx & 7;
            uint32_t dsw = (uint32_t)row*128 + (((uint32_t)ch ^ (row&7))<<4);
            const float* src = W + (size_t)row*Cn + kcol + ch*4;
            CP16(base + 8192u + dsw, src, 16);
        }
    };
    // A staging (cp.async, non-LNA path)
    auto stageA = [&](int buf, int it) {
        int shift = (CONV && it < 8) ? d : 0;
        int kcol = (it & 7) * 32;
        uint32_t base = sb + buf*STAGE;
        #pragma unroll
        for (int i = 0; i < 2; i++) {
            int row = a_row0 + 32*i;
            uint32_t dsw = (uint32_t)row*128 + (((uint32_t)a_ch ^ (row&7))<<4);
            int gm = row0 + row;
            int ok = (shift == 0) || ((gm & (Sn-1)) >= shift);
            const float* src = A + (size_t)(gm - shift)*Cn + kcol + a_ch*4;
            CP16(base + dsw, src, ok ? 16 : 0);
        }
    };
    // A staging for LNA: split load / transform+store
    auto aload = [&](int it, float4* v) {
        int kcol = it * 32;
        #pragma unroll
        for (int i = 0; i < 2; i++) {
            int gm = row0 + a_row0 + 32*i;
            v[i] = *(const float4*)(A + (size_t)gm*Cn + kcol + a_ch*4);
        }
    };
    auto astore = [&](int buf, int it, const float4* v) {
        int kcol = it * 32;
        float4 g4 = *(const float4*)(ag + kcol + a_ch*4);
        float4 b4 = *(const float4*)(ab + kcol + a_ch*4);
        #pragma unroll
        for (int i = 0; i < 2; i++) {
            int row = a_row0 + 32*i;
            uint32_t dsw = (uint32_t)row*128 + (((uint32_t)a_ch ^ (row&7))<<4);
            float4 y;
            y.x = (v[i].x - mu_[i])*rs_[i]*g4.x + b4.x;
            y.y = (v[i].y - mu_[i])*rs_[i]*g4.y + b4.y;
            y.z = (v[i].z - mu_[i])*rs_[i]*g4.z + b4.z;
            y.w = (v[i].w - mu_[i])*rs_[i]*g4.w + b4.w;
            y.x = y.x >= 0.f ? y.x : 0.01f*y.x;
            y.y = y.y >= 0.f ? y.y : 0.01f*y.y;
            y.z = y.z >= 0.f ? y.z : 0.01f*y.z;
            y.w = y.w >= 0.f ? y.w : 0.01f*y.w;
            *(float4*)(smem + (size_t)buf*STAGE + dsw) = y;
        }
    };

    auto compute = [&](int it) {
        uint32_t base = sb + (it & 1)*STAGE;
        uint32_t aT = base, bT = base + 8192u;
        #pragma unroll
        for (int ks = 0; ks < 32; ks += 8) {
            uint32_t ksx = (uint32_t)(ks << 2);
            uint32_t afr[2][4];
            ldsm4(afr[0], aT + (aLM[0] ^ ksx));
            ldsm4(afr[1], aT + (aLM[1] ^ ksx));
            uint32_t bfr[4][4];
            #pragma unroll
            for (int nip = 0; nip < 4; nip++)
                ldsm4(bfr[nip], bT + (bLM[nip] ^ ksx));
            #pragma unroll
            for (int mi = 0; mi < 2; mi++)
                #pragma unroll
                for (int ni = 0; ni < 8; ni++)
                    mma_tf32(acc[mi][ni], afr[mi], &bfr[ni>>1][(ni&1)*2]);
        }
    };

    if (LNA) {
        float4 v0[2];
        aload(0, v0);
        astore(0, 0, v0);      // prologue: exposed once
        stageB(0, 0); CPCOMMIT();
        float4 vn[2];
        for (int it = 0; it < KITERS; it++) {
            if (it < KITERS-1) {
                stageB((it+1) & 1, it+1); CPCOMMIT();
                aload(it+1, vn);
                CPWAIT(1);
            } else CPWAIT(0);
            __syncthreads();
            compute(it);
            if (it < KITERS-1) astore((it+1) & 1, it+1, vn);
            __syncthreads();
        }
    } else {
        stageA(0, 0); stageB(0, 0); CPCOMMIT();
        for (int it = 0; it < KITERS; it++) {
            if (it < KITERS-1) {
                stageA((it+1) & 1, it+1);
                stageB((it+1) & 1, it+1);
                CPCOMMIT();
                CPWAIT(1);
            } else CPWAIT(0);
            __syncthreads();
            compute(it);
            __syncthreads();
        }
    }

    // ---- epilogue: bias + row LayerNorm + lrelu
    float rsum[2][2] = {{0.f,0.f},{0.f,0.f}};
    float rsq [2][2] = {{0.f,0.f},{0.f,0.f}};
    #pragma unroll
    for (int mi = 0; mi < 2; mi++)
        #pragma unroll
        for (int ni = 0; ni < 8; ni++) {
            int c = n_base + ni*8 + tq*2;
            float bx = bias[c], by = bias[c+1];
            #pragma unroll
            for (int half = 0; half < 2; half++) {
                float v0 = acc[mi][ni][half*2+0] + bx;
                float v1 = acc[mi][ni][half*2+1] + by;
                acc[mi][ni][half*2+0] = v0;
                acc[mi][ni][half*2+1] = v1;
                rsum[mi][half] += v0 + v1;
                rsq [mi][half] += v0*v0 + v1*v1;
            }
        }
    #pragma unroll
    for (int off = 1; off < 4; off <<= 1)
        #pragma unroll
        for (int mi = 0; mi < 2; mi++)
            #pragma unroll
            for (int half = 0; half < 2; half++) {
                rsum[mi][half] += __shfl_xor_sync(0xffffffffu, rsum[mi][half], off);
                rsq [mi][half] += __shfl_xor_sync(0xffffffffu, rsq [mi][half], off);
            }
    float2* red = (float2*)smem;
    if (tq == 0) {
        #pragma unroll
        for (int mi = 0; mi < 2; mi++)
            #pragma unroll
            for (int half = 0; half < 2; half++) {
                int r = m_base + mi*16 + half*8 + g;
                red[r*4 + warp_n] = make_float2(rsum[mi][half], rsq[mi][half]);
            }
    }
    __syncthreads();
    #pragma unroll
    for (int mi = 0; mi < 2; mi++)
        #pragma unroll
        for (int half = 0; half < 2; half++) {
            int r = m_base + mi*16 + half*8 + g;
            float2 p0 = red[r*4+0], p1 = red[r*4+1], p2 = red[r*4+2], p3 = red[r*4+3];
            float s = p0.x + p1.x + p2.x + p3.x;
            float q = p0.y + p1.y + p2.y + p3.y;
            float mu = s * (1.0f/Cn);
            float var = q * (1.0f/Cn) - mu*mu;
            float rs = rsqrtf(var + EPSn);
            size_t rowg = (size_t)(row0 + r);
            #pragma unroll
            for (int ni = 0; ni < 8; ni++) {
                int c = n_base + ni*8 + tq*2;
                float gx = gamma[c], gy = gamma[c+1];
                float bx = beta[c],  by = beta[c+1];
                float y0 = (acc[mi][ni][half*2+0] - mu)*rs*gx + bx;
                float y1 = (acc[mi][ni][half*2+1] - mu)*rs*gy + by;
                y0 = y0 >= 0.f ? y0 : 0.01f*y0;
                y1 = y1 >= 0.f ? y1 : 0.01f*y1;
                *(float2*)(out + rowg*Cn + c) = make_float2(y0, y1);
            }
        }
}

// ---------------------------------------------------------------------------
// Fused gate: E = A@We^T + be, G = A@Wg^T + bg, h += E*sigmoid(G).
// Also writes per-row (sum,sumsq) partials of new h into accH[nhalf*Mn + m].
// Tile 64x128x32; grid = (2, Mn/64) so both n-halves of the same rows are
// schedule-adjacent (A re-read hits L2). 8 warps (2x4), warp tile 32x32/output.
__global__ __launch_bounds__(256, 2) void gate_gemm_kernel(
    const float* __restrict__ A,
    const float* __restrict__ WeT, const float* __restrict__ WgT,
    const float* __restrict__ be, const float* __restrict__ bg,
    float* __restrict__ h, float2* __restrict__ accH)
{
    extern __shared__ __align__(128) char smem[];
    const uint32_t STAGE = 40960u;  // A 8KB + B0 16KB + B1 16KB
    uint32_t sb = smem_u32(smem);

    int tid = threadIdx.x;
    int wid = tid >> 5, lane = tid & 31;
    int g = lane >> 2, tq = lane & 3;
    int warp_m = wid >> 2, warp_n = wid & 3;
    int m_base = warp_m * 32, n_base = warp_n * 32;
    int nhalf = blockIdx.x;
    int row0 = blockIdx.y * 64, n0 = nhalf * 128;

    float accE[2][4][4], accG[2][4][4];
    #pragma unroll
    for (int i = 0; i < 2; i++)
        #pragma unroll
        for (int j = 0; j < 4; j++)
            #pragma unroll
            for (int q = 0; q < 4; q++) { accE[i][j][q] = 0.f; accG[i][j][q] = 0.f; }

    int lj = lane >> 3, lr = lane & 7;
    int j1 = lj & 1, j2 = lj >> 1;
    uint32_t aLM[2], bLM[2];
    #pragma unroll
    for (int mi = 0; mi < 2; mi++) {
        int rl = m_base + mi*16 + j1*8 + lr;
        aLM[mi] = (uint32_t)rl*128 + (((uint32_t)(j2 ^ lr))<<4);
    }
    #pragma unroll
    for (int nip = 0; nip < 2; nip++) {
        int rl = n_base + nip*16 + j2*8 + lr;
        bLM[nip] = (uint32_t)rl*128 + (((uint32_t)(j1 ^ lr))<<4);
    }

    auto stage = [&](int buf, int kt) {
        uint32_t base = sb + buf*STAGE;
        #pragma unroll
        for (int i = 0; i < 2; i++) {
            int cidx = tid + 256*i;
            int row = cidx >> 3, ch = cidx & 7;
            uint32_t dsw = (uint32_t)row*128 + (((uint32_t)ch ^ (row&7))<<4);
            const float* src = A + (size_t)(row0 + row)*Cn + kt + ch*4;
            CP16(base + dsw, src, 16);
        }
        #pragma unroll
        for (int tap = 0; tap < 2; tap++) {
            const float* W = tap ? WgT : WeT;
            uint32_t bT = base + 8192u + tap*16384u;
            #pragma unroll
            for (int i = 0; i < 4; i++) {
                int cidx = tid + 256*i;
                int row = cidx >> 3, ch = cidx & 7;
                uint32_t dsw = (uint32_t)row*128 + (((uint32_t)ch ^ (row&7))<<4);
                const float* src = W + (size_t)(n0 + row)*Cn + kt + ch*4;
                CP16(bT + dsw, src, 16);
            }
        }
    };

    stage(0, 0);
    CPCOMMIT();

    for (int it = 0; it < 8; it++) {
        if (it < 7) {
            stage((it+1) & 1, (it+1)*32);
            CPCOMMIT();
            CPWAIT(1);
        } else {
            CPWAIT(0);
        }
        __syncthreads();
        uint32_t base = sb + (it & 1)*STAGE;
        uint32_t aT = base;
        uint32_t bTe = base + 8192u;
        uint32_t bTg = base + 8192u + 16384u;
        #pragma unroll
        for (int ks = 0; ks < 32; ks += 8) {
            uint32_t ksx = (uint32_t)(ks << 2);
            uint32_t afr[2][4];
            ldsm4(afr[0], aT + (aLM[0] ^ ksx));
            ldsm4(afr[1], aT + (aLM[1] ^ ksx));
            uint32_t beF[2][4], bgF[2][4];
            #pragma unroll
            for (int nip = 0; nip < 2; nip++) {
                ldsm4(beF[nip], bTe + (bLM[nip] ^ ksx));
                ldsm4(bgF[nip], bTg + (bLM[nip] ^ ksx));
            }
            #pragma unroll
            for (int mi = 0; mi < 2; mi++)
                #pragma unroll
                for (int ni = 0; ni < 4; ni++) {
                    mma_tf32(accE[mi][ni], afr[mi], &beF[ni>>1][(ni&1)*2]);
                    mma_tf32(accG[mi][ni], afr[mi], &bgF[ni>>1][(ni&1)*2]);
                }
        }
        __syncthreads();
    }

    // ---- epilogue: h += E * sigmoid(G), accumulate row partials
    float rsum[2][2] = {{0.f,0.f},{0.f,0.f}};
    float rsq [2][2] = {{0.f,0.f},{0.f,0.f}};
    #pragma unroll
    for (int mi = 0; mi < 2; mi++) {
        int r0g = row0 + m_base + mi*16 + g;
        #pragma unroll
        for (int ni = 0; ni < 4; ni++) {
            int c = n0 + n_base + ni*8 + tq*2;
            float bex = be[c], bey = be[c+1];
            float bgx = bg[c], bgy = bg[c+1];
            #pragma unroll
            for (int half = 0; half < 2; half++) {
                size_t r = (size_t)(r0g + half*8);
                float e0 = accE[mi][ni][half*2+0] + bex;
                float e1 = accE[mi][ni][half*2+1] + bey;
                float q0 = accG[mi][ni][half*2+0] + bgx;
                float q1 = accG[mi][ni][half*2+1] + bgy;
                float2 hv = *(float2*)(h + r*Cn + c);
                float h0 = hv.x + e0 * (1.f/(1.f + __expf(-q0)));
                float h1 = hv.y + e1 * (1.f/(1.f + __expf(-q1)));
                *(float2*)(h + r*Cn + c) = make_float2(h0, h1);
                rsum[mi][half] += h0 + h1;
                rsq [mi][half] += h0*h0 + h1*h1;
            }
        }
    }
    // quad reduce over tq
    #pragma unroll
    for (int off = 1; off < 4; off <<= 1)
        #pragma unroll
        for (int mi = 0; mi < 2; mi++)
            #pragma unroll
            for (int half = 0; half < 2; half++) {
                rsum[mi][half] += __shfl_xor_sync(0xffffffffu, rsum[mi][half], off);
                rsq [mi][half] += __shfl_xor_sync(0xffffffffu, rsq [mi][half], off);
            }
    float2* red = (float2*)smem;    // 64 rows x 4 n-warps (smem free after loop)
    if (tq == 0) {
        #pragma unroll
        for (int mi = 0; mi < 2; mi++)
            #pragma unroll
            for (int half = 0; half < 2; half++) {
                int r = m_base + mi*16 + half*8 + g;
                red[r*4 + warp_n] = make_float2(rsum[mi][half], rsq[mi][half]);
            }
    }
    __syncthreads();
    if (warp_n == 0 && tq == 0) {
        #pragma unroll
        for (int mi = 0; mi < 2; mi++)
            #pragma unroll
            for (int half = 0; half < 2; half++) {
                int r = m_base + mi*16 + half*8 + g;
                float2 p0 = red[r*4+0], p1 = red[r*4+1], p2 = red[r*4+2], p3 = red[r*4+3];
                accH[(size_t)nhalf*Mn + row0 + r] =
                    make_float2(p0.x + p1.x + p2.x + p3.x,
                                p0.y + p1.y + p2.y + p3.y);
            }
    }
}

// ---------------------------------------------------------------------------
__global__ __launch_bounds__(256) void latent_kernel(
    const float* __restrict__ z, const float* __restrict__ W,
    const float* __restrict__ bias)
{
    __shared__ float zs[Cn];
    int b = blockIdx.x, c = threadIdx.x;
    zs[c] = z[b*Cn + c];
    __syncthreads();
    float acc = bias[c];
    #pragma unroll 4
    for (int k = 0; k < Cn; k++) acc += zs[k] * W[k*Cn + c];
    g_lat[b*Cn + c] = acc;
}

// h = emb[x] + lat;  a = lrelu(ln1_0(h)).  One warp per row.
__global__ __launch_bounds__(256) void embed_ln_kernel(
    const int* __restrict__ x, const float* __restrict__ emb,
    const float* __restrict__ gamma, const float* __restrict__ beta)
{
    int warp = threadIdx.x >> 5, lane = threadIdx.x & 31;
    int m = blockIdx.x*8 + warp;
    int b = m >> 9;
    int tok = x[m];
    const float4* er = (const float4*)(emb + (size_t)tok*Cn);
    const float4* lr = (const float4*)(g_lat + (size_t)b*Cn);
    float4 v0 = er[lane],      l0 = lr[lane];
    float4 v1 = er[lane + 32], l1 = lr[lane + 32];
    v0.x += l0.x; v0.y += l0.y; v0.z += l0.z; v0.w += l0.w;
    v1.x += l1.x; v1.y += l1.y; v1.z += l1.z; v1.w += l1.w;
    float4* hrow = (float4*)(g_h + (size_t)m*Cn);
    hrow[lane]      = v0;
    hrow[lane + 32] = v1;
    float s = v0.x+v0.y+v0.z+v0.w + v1.x+v1.y+v1.z+v1.w;
    float q = v0.x*v0.x+v0.y*v0.y+v0.z*v0.z+v0.w*v0.w
            + v1.x*v1.x+v1.y*v1.y+v1.z*v1.z+v1.w*v1.w;
    #pragma unroll
    for (int o = 16; o; o >>= 1) {
        s += __shfl_xor_sync(0xffffffffu, s, o);
        q += __shfl_xor_sync(0xffffffffu, q, o);
    }
    float mu = s * (1.0f/Cn);
    float var = q * (1.0f/Cn) - mu*mu;
    float rs = rsqrtf(var + EPSn);
    int c0 = lane*4, c1 = 128 + lane*4;
    float4 ga = *(const float4*)(gamma + c0);
    float4 gb = *(const float4*)(gamma + c1);
    float4 ba = *(const float4*)(beta  + c0);
    float4 bb = *(const float4*)(beta  + c1);
    float4 o0, o1;
    #define LNA_(xv, gg, bbv) ({ float y = (xv - mu)*rs*gg + bbv; y >= 0.f ? y : 0.01f*y; })
    o0.x = LNA_(v0.x, ga.x, ba.x); o0.y = LNA_(v0.y, ga.y, ba.y);
    o0.z = LNA_(v0.z, ga.z, ba.z); o0.w = LNA_(v0.w, ga.w, ba.w);
    o1.x = LNA_(v1.x, gb.x, bb.x); o1.y = LNA_(v1.y, gb.y, bb.y);
    o1.z = LNA_(v1.z, gb.z, bb.z); o1.w = LNA_(v1.w, gb.w, bb.w);
    #undef LNA_
    float4* arow = (float4*)(g_a + (size_t)m*Cn);
    arow[lane]      = o0;
    arow[lane + 32] = o1;
}

// head: 512 threads, 16 tokens/block (one warp per token), dynamic smem.
__global__ __launch_bounds__(512) void head_kernel(
    const int* __restrict__ x, const float* __restrict__ outW,
    const float* __restrict__ outb, float* __restrict__ out)
{
    extern __shared__ float hsm[];
    float* Ws = hsm;                 // [256][33]
    float* hs = hsm + Cn*(Vn+1);     // [16][256]
    int tid = threadIdx.x;
    for (int i = tid; i < Cn*Vn; i += 512)
        Ws[(i >> 5)*(Vn+1) + (i & 31)] = outW[i];
    int warp = tid >> 5, lane = tid & 31;
    int m = blockIdx.x*16 + warp;
    const float4* hr = (const float4*)(g_h + (size_t)m*Cn);
    ((float4*)(hs + warp*Cn))[lane]      = hr[lane];
    ((float4*)(hs + warp*Cn))[lane + 32] = hr[lane + 32];
    __syncthreads();
    float acc = outb[lane];
    const float* hrow = hs + warp*Cn;
    #pragma unroll 8
    for (int k = 0; k < Cn; k++)
        acc += hrow[k] * Ws[k*(Vn+1) + lane];
    float mx = acc;
    #pragma unroll
    for (int o = 16; o; o >>= 1) mx = fmaxf(mx, __shfl_xor_sync(0xffffffffu, mx, o));
    float ex = expf(acc - mx), sum = ex;
    #pragma unroll
    for (int o = 16; o; o >>= 1) sum += __shfl_xor_sync(0xffffffffu, sum, o);
    float lse = mx + logf(sum);
    int b = m >> 9, s = m & (Sn-1);
    if (s < Sn-1) {
        int tgt = x[m + 1];
        float lt = __shfl_sync(0xffffffffu, acc, tgt);
        if (lane == 0) out[(size_t)b*(Sn-1) + s] = lt - lse;
    }
}

// ---------------------------------------------------------------------------
extern "C" void kernel_launch(void* const* d_in, const int* in_sizes, int n_in,
                              void* d_out, int out_size)
{
    const int*   x    = (const int*)  d_in[0];
    const float* z    = (const float*)d_in[1];
    const float* emb  = (const float*)d_in[2];
    const float* latW = (const float*)d_in[3];
    const float* latb = (const float*)d_in[4];
    const float* ln1g = (const float*)d_in[5];
    const float* ln1b = (const float*)d_in[6];
    const float* w1   = (const float*)d_in[7];
    const float* b1   = (const float*)d_in[8];
    const float* ln2g = (const float*)d_in[9];
    const float* ln2b = (const float*)d_in[10];
    const float* wd   = (const float*)d_in[11];
    const float* bd   = (const float*)d_in[12];
    const float* ln3g = (const float*)d_in[13];
    const float* ln3b = (const float*)d_in[14];
    const float* we   = (const float*)d_in[15];
    const float* be   = (const float*)d_in[16];
    const float* wg   = (const float*)d_in[17];
    const float* bg   = (const float*)d_in[18];
    const float* outW = (const float*)d_in[19];
    const float* outb = (const float*)d_in[20];

    float *hP, *aP, *tP, *wtP;
    float2* accP;
    cudaGetSymbolAddress((void**)&hP, g_h);
    cudaGetSymbolAddress((void**)&aP, g_a);
    cudaGetSymbolAddress((void**)&tP, g_t);
    cudaGetSymbolAddress((void**)&wtP, g_wt);
    cudaGetSymbolAddress((void**)&accP, g_acc);

    const int SMEMLN = 81920;    // 2 stages x 40KB
    const int SMEMG  = 81920;
    const int SMEMH  = (Cn*(Vn+1) + 16*Cn) * 4;   // 50176
    cudaFuncSetAttribute(gemm_ln_kernel<8,false,false>, cudaFuncAttributeMaxDynamicSharedMemorySize, SMEMLN);
    cudaFuncSetAttribute(gemm_ln_kernel<8,false,true>,  cudaFuncAttributeMaxDynamicSharedMemorySize, SMEMLN);
    cudaFuncSetAttribute(gemm_ln_kernel<16,true,false>, cudaFuncAttributeMaxDynamicSharedMemorySize, SMEMLN);
    cudaFuncSetAttribute(gate_gemm_kernel, cudaFuncAttributeMaxDynamicSharedMemorySize, SMEMG);
    cudaFuncSetAttribute(head_kernel, cudaFuncAttributeMaxDynamicSharedMemorySize, SMEMH);

    dim3 tgrid(8, 8, 35);
    transpose_w_kernel<<<tgrid, 256>>>(w1, wd, we, wg);
    latent_kernel<<<Bn, Cn>>>(z, latW, latb);
    embed_ln_kernel<<<Mn/8, 256>>>(x, emb, ln1g, ln1b);

    dim3 ggridG(2, Mn/64);
    const size_t CC = (size_t)Cn*Cn;

    for (int i = 0; i < NLn; i++) {
        int d = 1 << i;
        // t = lrelu(ln2( ln1_i-applied-A @ w1 + b1 ))
        if (i == 0)
            gemm_ln_kernel<8,false,false><<<Mn/64, 256, SMEMLN>>>(
                aP, wtP + (i*5+0)*CC, nullptr, b1 + i*Cn,
                ln2g + i*Cn, ln2b + i*Cn, tP, 0,
                nullptr, nullptr, nullptr);
        else
            gemm_ln_kernel<8,false,true><<<Mn/64, 256, SMEMLN>>>(
                hP, wtP + (i*5+0)*CC, nullptr, b1 + i*Cn,
                ln2g + i*Cn, ln2b + i*Cn, tP, 0,
                accP, ln1g + i*Cn, ln1b + i*Cn);
        // a = lrelu(ln3(shift(t,d) @ wd0 + t @ wd1 + bd))
        gemm_ln_kernel<16,true,false><<<Mn/64, 256, SMEMLN>>>(
            tP, wtP + (i*5+1)*CC, wtP + (i*5+2)*CC, bd + i*Cn,
            ln3g + i*Cn, ln3b + i*Cn, aP, d,
            nullptr, nullptr, nullptr);
        // h += (a@we+be)*sigmoid(a@wg+bg); row partials -> g_acc
        gate_gemm_kernel<<<ggridG, 256, SMEMG>>>(aP, wtP + (i*5+3)*CC, wtP + (i*5+4)*CC,
                                                 be + i*Cn, bg + i*Cn, hP, accP);
    }

    head_kernel<<<Mn/16, 512, SMEMH>>>(x, outW, outb, (float*)d_out);
}

// round 14
// speedup vs baseline: 1.4176x; 1.4176x over previous
#include <cuda_runtime.h>
#include <cuda_fp16.h>
#include <cstdint>

// Problem dims
#define Bn   256
#define Sn   512
#define Cn   256
#define Vn   32
#define NLn  7
#define Mn   (Bn*Sn)
#define EPSn 1e-5f

// Scratch
__device__ float  g_h[(size_t)Mn*Cn];          // residual (fp32)
__device__ __half g_a[(size_t)Mn*Cn];          // activations (fp16)
__device__ __half g_t[(size_t)Mn*Cn];
__device__ float  g_lat[Bn*Cn];
__device__ __half g_wt[35*65536];              // fp16 transposed weights [35][N][K]
__device__ float2 g_acc[2*Mn];                 // per-row (sum,sumsq) of h, per n-half

// ---------------------------------------------------------------------------
__device__ __forceinline__ uint32_t smem_u32(const void* p) {
    uint32_t a;
    asm("{ .reg .u64 t; cvta.to.shared.u64 t, %1; cvt.u32.u64 %0, t; }"
        : "=r"(a) : "l"(p));
    return a;
}
#define CP16(dst, src, sz) \
    asm volatile("cp.async.cg.shared.global [%0], [%1], 16, %2;" \
        :: "r"(dst), "l"(src), "r"(sz))
#define CPCOMMIT() asm volatile("cp.async.commit_group;")
#define CPWAIT(n)  asm volatile("cp.async.wait_group %0;" :: "n"(n))

__device__ __forceinline__ void ldsm4(uint32_t* r, uint32_t addr) {
    asm volatile("ldmatrix.sync.aligned.m8n8.x4.shared.b16 {%0,%1,%2,%3}, [%4];"
        : "=r"(r[0]), "=r"(r[1]), "=r"(r[2]), "=r"(r[3]) : "r"(addr));
}

__device__ __forceinline__ void mma_f16(float* c, const uint32_t* a, const uint32_t* b) {
    asm volatile(
        "mma.sync.aligned.m16n8k16.row.col.f32.f16.f16.f32 "
        "{%0,%1,%2,%3}, {%4,%5,%6,%7}, {%8,%9}, {%0,%1,%2,%3};"
        : "+f"(c[0]), "+f"(c[1]), "+f"(c[2]), "+f"(c[3])
        : "r"(a[0]), "r"(a[1]), "r"(a[2]), "r"(a[3]), "r"(b[0]), "r"(b[1]));
}

// ---------------------------------------------------------------------------
// Weight transpose+convert: g_wt[mat][n][k] = (half)W[k][n]
__global__ __launch_bounds__(256) void transpose_w_kernel(
    const float* __restrict__ w1, const float* __restrict__ wd,
    const float* __restrict__ we, const float* __restrict__ wg)
{
    __shared__ float t[32][33];
    int mat = blockIdx.z;
    int layer = mat / 5, wh = mat % 5;
    const size_t CC = 65536;
    const float* src;
    if      (wh == 0) src = w1 + (size_t)layer*CC;
    else if (wh == 1) src = wd + (size_t)layer*2*CC;
    else if (wh == 2) src = wd + (size_t)layer*2*CC + CC;
    else if (wh == 3) src = we + (size_t)layer*CC;
    else              src = wg + (size_t)layer*CC;
    int tx = threadIdx.x & 31, ty = threadIdx.x >> 5;
    int k0 = blockIdx.x*32, n0 = blockIdx.y*32;
    #pragma unroll
    for (int j = 0; j < 32; j += 8)
        t[ty+j][tx] = src[(size_t)(k0+ty+j)*256 + n0 + tx];
    __syncthreads();
    __half* dst = g_wt + (size_t)mat*CC;
    #pragma unroll
    for (int j = 0; j < 32; j += 8)
        dst[(size_t)(n0+ty+j)*256 + k0 + tx] = __float2half(t[tx][ty+j]);
}

// ---------------------------------------------------------------------------
// fp16 GEMM + fused LayerNorm+lrelu epilogue.
// Tile 64x256, BK=64 (128B rows fp16), 8 warps (2m x 4n), warp tile 32x64.
// LNA=true: A operand = ln1(h) computed during staging (stats from accH).
template<int KITERS, bool CONV, bool LNA>
__global__ __launch_bounds__(256, 2) void gemm_ln_kernel(
    const __half* __restrict__ Ah, const float* __restrict__ Af,
    const __half* __restrict__ W0t, const __half* __restrict__ W1t,
    const float* __restrict__ bias,
    const float* __restrict__ gamma, const float* __restrict__ beta,
    __half* __restrict__ out, int d,
    const float2* __restrict__ accH,
    const float* __restrict__ ag, const float* __restrict__ ab)
{
    extern __shared__ __align__(128) char smem[];
    const uint32_t STAGE = 40960u;   // A 8KB + B 32KB
    uint32_t sb = smem_u32(smem);

    int tid = threadIdx.x;
    int wid = tid >> 5, lane = tid & 31;
    int g = lane >> 2, tq = lane & 3;
    int warp_m = wid >> 2, warp_n = wid & 3;
    int m_base = warp_m * 32, n_base = warp_n * 64;
    int row0 = blockIdx.x * 64;

    float acc[2][8][4];
    #pragma unroll
    for (int i = 0; i < 2; i++)
        #pragma unroll
        for (int j = 0; j < 8; j++)
            #pragma unroll
            for (int q = 0; q < 4; q++) acc[i][j][q] = 0.f;

    // ldmatrix lane constants (m16n8k16 fragment layout)
    int lr = lane & 7;
    int mh = (lane >> 3) & 1;   // A: m-half     B: k-half
    int kh = lane >> 4;         // A: k-half     B: n-half
    uint32_t aLM[2], bLM[4];
    #pragma unroll
    for (int mi = 0; mi < 2; mi++) {
        int rl = m_base + mi*16 + mh*8 + lr;
        aLM[mi] = (uint32_t)rl*128 + (((uint32_t)(kh ^ lr))<<4);
    }
    #pragma unroll
    for (int nip = 0; nip < 4; nip++) {
        int rl = n_base + nip*16 + kh*8 + lr;
        bLM[nip] = (uint32_t)rl*128 + (((uint32_t)(mh ^ lr))<<4);
    }

    // staging constants: chunk = 8 halves = 16B; 8 chunks/row
    int a_row0 = tid >> 3;          // 0..31 -> rows r, r+32
    int a_ch   = tid & 7;
    float mu_[2], rs_[2];
    if (LNA) {
        #pragma unroll
        for (int i = 0; i < 2; i++) {
            int gm = row0 + a_row0 + 32*i;
            float2 p0 = accH[gm];
            float2 p1 = accH[Mn + gm];
            float s = p0.x + p1.x, q = p0.y + p1.y;
            float m = s * (1.0f/Cn);
            mu_[i] = m;
            rs_[i] = rsqrtf(q * (1.0f/Cn) - m*m + EPSn);
        }
    }

    auto stageB = [&](int buf, int it) {
        const __half* W = (CONV && it >= KITERS/2) ? W1t : W0t;
        int kit = CONV ? (it & (KITERS/2 - 1)) : it;   // FIX: full K range when !CONV
        int kcol = kit * 64;
        uint32_t base = sb + buf*STAGE;
        #pragma unroll
        for (int i = 0; i < 8; i++) {
            int cidx = tid + 256*i;
            int row = cidx >> 3, ch = cidx & 7;
            uint32_t dsw = (uint32_t)row*128 + (((uint32_t)ch ^ (row&7))<<4);
            const __half* src = W + (size_t)row*Cn + kcol + ch*8;
            CP16(base + 8192u + dsw, src, 16);
        }
    };
    auto stageA = [&](int buf, int it) {     // non-LNA (fp16 source)
        int shift = (CONV && it < KITERS/2) ? d : 0;
        int kit = CONV ? (it & (KITERS/2 - 1)) : it;   // FIX
        int kcol = kit * 64;
        uint32_t base = sb + buf*STAGE;
        #pragma unroll
        for (int i = 0; i < 2; i++) {
            int row = a_row0 + 32*i;
            uint32_t dsw = (uint32_t)row*128 + (((uint32_t)a_ch ^ (row&7))<<4);
            int gm = row0 + row;
            int ok = (shift == 0) || ((gm & (Sn-1)) >= shift);
            const __half* src = Ah + (size_t)(gm - shift)*Cn + kcol + a_ch*8;
            CP16(base + dsw, src, ok ? 16 : 0);
        }
    };
    // LNA: fp32 h -> ln -> fp16 STS
    auto aload = [&](int it, float4* v) {
        int kcol = it * 64;
        #pragma unroll
        for (int i = 0; i < 2; i++) {
            const float* src = Af + (size_t)(row0 + a_row0 + 32*i)*Cn + kcol + a_ch*8;
            v[2*i]   = *(const float4*)(src);
            v[2*i+1] = *(const float4*)(src + 4);
        }
    };
    auto astore = [&](int buf, int it, const float4* v) {
        int kcol = it * 64;
        float ga[8], ba[8];
        *(float4*)(ga)     = *(const float4*)(ag + kcol + a_ch*8);
        *(float4*)(ga + 4) = *(const float4*)(ag + kcol + a_ch*8 + 4);
        *(float4*)(ba)     = *(const float4*)(ab + kcol + a_ch*8);
        *(float4*)(ba + 4) = *(const float4*)(ab + kcol + a_ch*8 + 4);
        #pragma unroll
        for (int i = 0; i < 2; i++) {
            int row = a_row0 + 32*i;
            uint32_t dsw = (uint32_t)row*128 + (((uint32_t)a_ch ^ (row&7))<<4);
            float vv[8];
            *(float4*)(vv)     = v[2*i];
            *(float4*)(vv + 4) = v[2*i+1];
            float y[8];
            #pragma unroll
            for (int e = 0; e < 8; e++) {
                float t = (vv[e] - mu_[i])*rs_[i]*ga[e] + ba[e];
                y[e] = t >= 0.f ? t : 0.01f*t;
            }
            __half2 p0 = __floats2half2_rn(y[0], y[1]);
            __half2 p1 = __floats2half2_rn(y[2], y[3]);
            __half2 p2 = __floats2half2_rn(y[4], y[5]);
            __half2 p3 = __floats2half2_rn(y[6], y[7]);
            uint4 pk;
            pk.x = *reinterpret_cast<uint32_t*>(&p0);
            pk.y = *reinterpret_cast<uint32_t*>(&p1);
            pk.z = *reinterpret_cast<uint32_t*>(&p2);
            pk.w = *reinterpret_cast<uint32_t*>(&p3);
            *(uint4*)(smem + (size_t)buf*STAGE + dsw) = pk;
        }
    };

    auto compute = [&](int it) {
        uint32_t base = sb + (it & 1)*STAGE;
        uint32_t aT = base, bT = base + 8192u;
        #pragma unroll
        for (int ks = 0; ks < 64; ks += 16) {
            uint32_t ksx = (uint32_t)(ks << 1);   // (ks/8)<<4 bytes
            uint32_t afr[2][4];
            ldsm4(afr[0], aT + (aLM[0] ^ ksx));
            ldsm4(afr[1], aT + (aLM[1] ^ ksx));
            uint32_t bfr[4][4];
            #pragma unroll
            for (int nip = 0; nip < 4; nip++)
                ldsm4(bfr[nip], bT + (bLM[nip] ^ ksx));
            #pragma unroll
            for (int mi = 0; mi < 2; mi++)
                #pragma unroll
                for (int ni = 0; ni < 8; ni++)
                    mma_f16(acc[mi][ni], afr[mi], &bfr[ni>>1][(ni&1)*2]);
        }
    };

    if (LNA) {
        float4 v0[4];
        aload(0, v0);
        astore(0, 0, v0);
        stageB(0, 0); CPCOMMIT();
        float4 vn[4];
        for (int it = 0; it < KITERS; it++) {
            if (it < KITERS-1) {
                stageB((it+1) & 1, it+1); CPCOMMIT();
                aload(it+1, vn);
                CPWAIT(1);
            } else CPWAIT(0);
            __syncthreads();
            compute(it);
            if (it < KITERS-1) astore((it+1) & 1, it+1, vn);
            __syncthreads();
        }
    } else {
        stageA(0, 0); stageB(0, 0); CPCOMMIT();
        for (int it = 0; it < KITERS; it++) {
            if (it < KITERS-1) {
                stageA((it+1) & 1, it+1);
                stageB((it+1) & 1, it+1);
                CPCOMMIT();
                CPWAIT(1);
            } else CPWAIT(0);
            __syncthreads();
            compute(it);
            __syncthreads();
        }
    }

    // ---- epilogue: bias + row LayerNorm + lrelu -> fp16 out
    float rsum[2][2] = {{0.f,0.f},{0.f,0.f}};
    float rsq [2][2] = {{0.f,0.f},{0.f,0.f}};
    #pragma unroll
    for (int mi = 0; mi < 2; mi++)
        #pragma unroll
        for (int ni = 0; ni < 8; ni++) {
            int c = n_base + ni*8 + tq*2;
            float bx = bias[c], by = bias[c+1];
            #pragma unroll
            for (int half = 0; half < 2; half++) {
                float v0 = acc[mi][ni][half*2+0] + bx;
                float v1 = acc[mi][ni][half*2+1] + by;
                acc[mi][ni][half*2+0] = v0;
                acc[mi][ni][half*2+1] = v1;
                rsum[mi][half] += v0 + v1;
                rsq [mi][half] += v0*v0 + v1*v1;
            }
        }
    #pragma unroll
    for (int off = 1; off < 4; off <<= 1)
        #pragma unroll
        for (int mi = 0; mi < 2; mi++)
            #pragma unroll
            for (int half = 0; half < 2; half++) {
                rsum[mi][half] += __shfl_xor_sync(0xffffffffu, rsum[mi][half], off);
                rsq [mi][half] += __shfl_xor_sync(0xffffffffu, rsq [mi][half], off);
            }
    float2* red = (float2*)smem;
    if (tq == 0) {
        #pragma unroll
        for (int mi = 0; mi < 2; mi++)
            #pragma unroll
            for (int half = 0; half < 2; half++) {
                int r = m_base + mi*16 + half*8 + g;
                red[r*4 + warp_n] = make_float2(rsum[mi][half], rsq[mi][half]);
            }
    }
    __syncthreads();
    #pragma unroll
    for (int mi = 0; mi < 2; mi++)
        #pragma unroll
        for (int half = 0; half < 2; half++) {
            int r = m_base + mi*16 + half*8 + g;
            float2 p0 = red[r*4+0], p1 = red[r*4+1], p2 = red[r*4+2], p3 = red[r*4+3];
            float s = p0.x + p1.x + p2.x + p3.x;
            float q = p0.y + p1.y + p2.y + p3.y;
            float mu = s * (1.0f/Cn);
            float var = q * (1.0f/Cn) - mu*mu;
            float rs = rsqrtf(var + EPSn);
            size_t rowg = (size_t)(row0 + r);
            #pragma unroll
            for (int ni = 0; ni < 8; ni++) {
                int c = n_base + ni*8 + tq*2;
                float gx = gamma[c], gy = gamma[c+1];
                float bx = beta[c],  by = beta[c+1];
                float y0 = (acc[mi][ni][half*2+0] - mu)*rs*gx + bx;
                float y1 = (acc[mi][ni][half*2+1] - mu)*rs*gy + by;
                y0 = y0 >= 0.f ? y0 : 0.01f*y0;
                y1 = y1 >= 0.f ? y1 : 0.01f*y1;
                *(__half2*)(out + rowg*Cn + c) = __floats2half2_rn(y0, y1);
            }
        }
}

// ---------------------------------------------------------------------------
// fp16 fused gate: E = A@We^T + be, G = A@Wg^T + bg, h += E*sigmoid(G).
// Writes per-row (sum,sumsq) of new h into accH[nhalf*Mn + m].
// Tile 64x128, BK=64, grid (Mn/64, 2). 8 warps (2x4), warp tile 32x32/output.
__global__ __launch_bounds__(256) void gate_gemm_kernel(
    const __half* __restrict__ A,
    const __half* __restrict__ WeT, const __half* __restrict__ WgT,
    const float* __restrict__ be, const float* __restrict__ bg,
    float* __restrict__ h, float2* __restrict__ accH)
{
    extern __shared__ __align__(128) char smem[];
    const uint32_t STAGE = 40960u;  // A 8KB + Be 16KB + Bg 16KB
    uint32_t sb = smem_u32(smem);

    int tid = threadIdx.x;
    int wid = tid >> 5, lane = tid & 31;
    int g = lane >> 2, tq = lane & 3;
    int warp_m = wid >> 2, warp_n = wid & 3;
    int m_base = warp_m * 32, n_base = warp_n * 32;
    int row0 = blockIdx.x * 64, nhalf = blockIdx.y, n0 = nhalf * 128;

    float accE[2][4][4], accG[2][4][4];
    #pragma unroll
    for (int i = 0; i < 2; i++)
        #pragma unroll
        for (int j = 0; j < 4; j++)
            #pragma unroll
            for (int q = 0; q < 4; q++) { accE[i][j][q] = 0.f; accG[i][j][q] = 0.f; }

    int lr = lane & 7;
    int mh = (lane >> 3) & 1;
    int kh = lane >> 4;
    uint32_t aLM[2], bLM[2];
    #pragma unroll
    for (int mi = 0; mi < 2; mi++) {
        int rl = m_base + mi*16 + mh*8 + lr;
        aLM[mi] = (uint32_t)rl*128 + (((uint32_t)(kh ^ lr))<<4);
    }
    #pragma unroll
    for (int nip = 0; nip < 2; nip++) {
        int rl = n_base + nip*16 + kh*8 + lr;
        bLM[nip] = (uint32_t)rl*128 + (((uint32_t)(mh ^ lr))<<4);
    }

    auto stage = [&](int buf, int it) {
        int kcol = it * 64;
        uint32_t base = sb + buf*STAGE;
        #pragma unroll
        for (int i = 0; i < 2; i++) {
            int cidx = tid + 256*i;
            int row = cidx >> 3, ch = cidx & 7;
            uint32_t dsw = (uint32_t)row*128 + (((uint32_t)ch ^ (row&7))<<4);
            const __half* src = A + (size_t)(row0 + row)*Cn + kcol + ch*8;
            CP16(base + dsw, src, 16);
        }
        #pragma unroll
        for (int tap = 0; tap < 2; tap++) {
            const __half* W = tap ? WgT : WeT;
            uint32_t bT = base + 8192u + tap*16384u;
            #pragma unroll
            for (int i = 0; i < 4; i++) {
                int cidx = tid + 256*i;
                int row = cidx >> 3, ch = cidx & 7;
                uint32_t dsw = (uint32_t)row*128 + (((uint32_t)ch ^ (row&7))<<4);
                const __half* src = W + (size_t)(n0 + row)*Cn + kcol + ch*8;
                CP16(bT + dsw, src, 16);
            }
        }
    };

    stage(0, 0);
    CPCOMMIT();

    for (int it = 0; it < 4; it++) {
        if (it < 3) {
            stage((it+1) & 1, it+1);
            CPCOMMIT();
            CPWAIT(1);
        } else {
            CPWAIT(0);
        }
        __syncthreads();
        uint32_t base = sb + (it & 1)*STAGE;
        uint32_t aT = base;
        uint32_t bTe = base + 8192u;
        uint32_t bTg = base + 8192u + 16384u;
        #pragma unroll
        for (int ks = 0; ks < 64; ks += 16) {
            uint32_t ksx = (uint32_t)(ks << 1);
            uint32_t afr[2][4];
            ldsm4(afr[0], aT + (aLM[0] ^ ksx));
            ldsm4(afr[1], aT + (aLM[1] ^ ksx));
            uint32_t beF[2][4], bgF[2][4];
            #pragma unroll
            for (int nip = 0; nip < 2; nip++) {
                ldsm4(beF[nip], bTe + (bLM[nip] ^ ksx));
                ldsm4(bgF[nip], bTg + (bLM[nip] ^ ksx));
            }
            #pragma unroll
            for (int mi = 0; mi < 2; mi++)
                #pragma unroll
                for (int ni = 0; ni < 4; ni++) {
                    mma_f16(accE[mi][ni], afr[mi], &beF[ni>>1][(ni&1)*2]);
                    mma_f16(accG[mi][ni], afr[mi], &bgF[ni>>1][(ni&1)*2]);
                }
        }
        __syncthreads();
    }

    // ---- epilogue: h += E * sigmoid(G), accumulate row partials
    float rsum[2][2] = {{0.f,0.f},{0.f,0.f}};
    float rsq [2][2] = {{0.f,0.f},{0.f,0.f}};
    #pragma unroll
    for (int mi = 0; mi < 2; mi++) {
        int r0g = row0 + m_base + mi*16 + g;
        #pragma unroll
        for (int ni = 0; ni < 4; ni++) {
            int c = n0 + n_base + ni*8 + tq*2;
            float bex = be[c], bey = be[c+1];
            float bgx = bg[c], bgy = bg[c+1];
            #pragma unroll
            for (int half = 0; half < 2; half++) {
                size_t r = (size_t)(r0g + half*8);
                float e0 = accE[mi][ni][half*2+0] + bex;
                float e1 = accE[mi][ni][half*2+1] + bey;
                float q0 = accG[mi][ni][half*2+0] + bgx;
                float q1 = accG[mi][ni][half*2+1] + bgy;
                float2 hv = *(float2*)(h + r*Cn + c);
                float h0 = hv.x + e0 * (1.f/(1.f + __expf(-q0)));
                float h1 = hv.y + e1 * (1.f/(1.f + __expf(-q1)));
                *(float2*)(h + r*Cn + c) = make_float2(h0, h1);
                rsum[mi][half] += h0 + h1;
                rsq [mi][half] += h0*h0 + h1*h1;
            }
        }
    }
    #pragma unroll
    for (int off = 1; off < 4; off <<= 1)
        #pragma unroll
        for (int mi = 0; mi < 2; mi++)
            #pragma unroll
            for (int half = 0; half < 2; half++) {
                rsum[mi][half] += __shfl_xor_sync(0xffffffffu, rsum[mi][half], off);
                rsq [mi][half] += __shfl_xor_sync(0xffffffffu, rsq [mi][half], off);
            }
    float2* red = (float2*)smem;
    if (tq == 0) {
        #pragma unroll
        for (int mi = 0; mi < 2; mi++)
            #pragma unroll
            for (int half = 0; half < 2; half++) {
                int r = m_base + mi*16 + half*8 + g;
                red[r*4 + warp_n] = make_float2(rsum[mi][half], rsq[mi][half]);
            }
    }
    __syncthreads();
    if (warp_n == 0 && tq == 0) {
        #pragma unroll
        for (int mi = 0; mi < 2; mi++)
            #pragma unroll
            for (int half = 0; half < 2; half++) {
                int r = m_base + mi*16 + half*8 + g;
                float2 p0 = red[r*4+0], p1 = red[r*4+1], p2 = red[r*4+2], p3 = red[r*4+3];
                accH[(size_t)nhalf*Mn + row0 + r] =
                    make_float2(p0.x + p1.x + p2.x + p3.x,
                                p0.y + p1.y + p2.y + p3.y);
            }
    }
}

// ---------------------------------------------------------------------------
__global__ __launch_bounds__(256) void latent_kernel(
    const float* __restrict__ z, const float* __restrict__ W,
    const float* __restrict__ bias)
{
    __shared__ float zs[Cn];
    int b = blockIdx.x, c = threadIdx.x;
    zs[c] = z[b*Cn + c];
    __syncthreads();
    float acc = bias[c];
    #pragma unroll 4
    for (int k = 0; k < Cn; k++) acc += zs[k] * W[k*Cn + c];
    g_lat[b*Cn + c] = acc;
}

// h = emb[x] + lat (fp32);  a = (half)lrelu(ln1_0(h)).  One warp per row.
__global__ __launch_bounds__(256) void embed_ln_kernel(
    const int* __restrict__ x, const float* __restrict__ emb,
    const float* __restrict__ gamma, const float* __restrict__ beta)
{
    int warp = threadIdx.x >> 5, lane = threadIdx.x & 31;
    int m = blockIdx.x*8 + warp;
    int b = m >> 9;
    int tok = x[m];
    const float4* er = (const float4*)(emb + (size_t)tok*Cn);
    const float4* lr = (const float4*)(g_lat + (size_t)b*Cn);
    float4 v0 = er[lane],      l0 = lr[lane];
    float4 v1 = er[lane + 32], l1 = lr[lane + 32];
    v0.x += l0.x; v0.y += l0.y; v0.z += l0.z; v0.w += l0.w;
    v1.x += l1.x; v1.y += l1.y; v1.z += l1.z; v1.w += l1.w;
    float4* hrow = (float4*)(g_h + (size_t)m*Cn);
    hrow[lane]      = v0;
    hrow[lane + 32] = v1;
    float s = v0.x+v0.y+v0.z+v0.w + v1.x+v1.y+v1.z+v1.w;
    float q = v0.x*v0.x+v0.y*v0.y+v0.z*v0.z+v0.w*v0.w
            + v1.x*v1.x+v1.y*v1.y+v1.z*v1.z+v1.w*v1.w;
    #pragma unroll
    for (int o = 16; o; o >>= 1) {
        s += __shfl_xor_sync(0xffffffffu, s, o);
        q += __shfl_xor_sync(0xffffffffu, q, o);
    }
    float mu = s * (1.0f/Cn);
    float var = q * (1.0f/Cn) - mu*mu;
    float rs = rsqrtf(var + EPSn);
    int c0 = lane*4, c1 = 128 + lane*4;
    float4 ga = *(const float4*)(gamma + c0);
    float4 gb = *(const float4*)(gamma + c1);
    float4 ba = *(const float4*)(beta  + c0);
    float4 bb = *(const float4*)(beta  + c1);
    #define LNA_(xv, gg, bbv) ({ float y = (xv - mu)*rs*gg + bbv; y >= 0.f ? y : 0.01f*y; })
    __half2* arow = (__half2*)(g_a + (size_t)m*Cn);
    arow[lane*2]       = __floats2half2_rn(LNA_(v0.x, ga.x, ba.x), LNA_(v0.y, ga.y, ba.y));
    arow[lane*2+1]     = __floats2half2_rn(LNA_(v0.z, ga.z, ba.z), LNA_(v0.w, ga.w, ba.w));
    arow[64 + lane*2]  = __floats2half2_rn(LNA_(v1.x, gb.x, bb.x), LNA_(v1.y, gb.y, bb.y));
    arow[64 + lane*2+1]= __floats2half2_rn(LNA_(v1.z, gb.z, bb.z), LNA_(v1.w, gb.w, bb.w));
    #undef LNA_
}

__global__ __launch_bounds__(256) void head_kernel(
    const int* __restrict__ x, const float* __restrict__ outW,
    const float* __restrict__ outb, float* __restrict__ out)
{
    __shared__ float Ws[Cn][Vn+1];
    __shared__ float hs[8][Cn];
    int tid = threadIdx.x;
    for (int i = tid; i < Cn*Vn; i += 256)
        Ws[i >> 5][i & 31] = outW[i];
    int warp = tid >> 5, lane = tid & 31;
    int m = blockIdx.x*8 + warp;
    const float4* hr = (const float4*)(g_h + (size_t)m*Cn);
    ((float4*)hs[warp])[lane]      = hr[lane];
    ((float4*)hs[warp])[lane + 32] = hr[lane + 32];
    __syncthreads();
    float acc = outb[lane];
    #pragma unroll 8
    for (int k = 0; k < Cn; k++)
        acc += hs[warp][k] * Ws[k][lane];
    float mx = acc;
    #pragma unroll
    for (int o = 16; o; o >>= 1) mx = fmaxf(mx, __shfl_xor_sync(0xffffffffu, mx, o));
    float ex = expf(acc - mx), sum = ex;
    #pragma unroll
    for (int o = 16; o; o >>= 1) sum += __shfl_xor_sync(0xffffffffu, sum, o);
    float lse = mx + logf(sum);
    int b = m >> 9, s = m & (Sn-1);
    if (s < Sn-1) {
        int tgt = x[m + 1];
        float lt = __shfl_sync(0xffffffffu, acc, tgt);
        if (lane == 0) out[(size_t)b*(Sn-1) + s] = lt - lse;
    }
}

// ---------------------------------------------------------------------------
extern "C" void kernel_launch(void* const* d_in, const int* in_sizes, int n_in,
                              void* d_out, int out_size)
{
    const int*   x    = (const int*)  d_in[0];
    const float* z    = (const float*)d_in[1];
    const float* emb  = (const float*)d_in[2];
    const float* latW = (const float*)d_in[3];
    const float* latb = (const float*)d_in[4];
    const float* ln1g = (const float*)d_in[5];
    const float* ln1b = (const float*)d_in[6];
    const float* w1   = (const float*)d_in[7];
    const float* b1   = (const float*)d_in[8];
    const float* ln2g = (const float*)d_in[9];
    const float* ln2b = (const float*)d_in[10];
    const float* wd   = (const float*)d_in[11];
    const float* bd   = (const float*)d_in[12];
    const float* ln3g = (const float*)d_in[13];
    const float* ln3b = (const float*)d_in[14];
    const float* we   = (const float*)d_in[15];
    const float* be   = (const float*)d_in[16];
    const float* wg   = (const float*)d_in[17];
    const float* bg   = (const float*)d_in[18];
    const float* outW = (const float*)d_in[19];
    const float* outb = (const float*)d_in[20];

    float *hP;
    __half *aP, *tP, *wtP;
    float2* accP;
    cudaGetSymbolAddress((void**)&hP, g_h);
    cudaGetSymbolAddress((void**)&aP, g_a);
    cudaGetSymbolAddress((void**)&tP, g_t);
    cudaGetSymbolAddress((void**)&wtP, g_wt);
    cudaGetSymbolAddress((void**)&accP, g_acc);

    const int SMEMLN = 81920;    // 2 stages x 40KB
    const int SMEMG  = 81920;
    cudaFuncSetAttribute(gemm_ln_kernel<4,false,false>, cudaFuncAttributeMaxDynamicSharedMemorySize, SMEMLN);
    cudaFuncSetAttribute(gemm_ln_kernel<4,false,true>,  cudaFuncAttributeMaxDynamicSharedMemorySize, SMEMLN);
    cudaFuncSetAttribute(gemm_ln_kernel<8,true,false>,  cudaFuncAttributeMaxDynamicSharedMemorySize, SMEMLN);
    cudaFuncSetAttribute(gate_gemm_kernel, cudaFuncAttributeMaxDynamicSharedMemorySize, SMEMG);

    dim3 tgrid(8, 8, 35);
    transpose_w_kernel<<<tgrid, 256>>>(w1, wd, we, wg);
    latent_kernel<<<Bn, Cn>>>(z, latW, latb);
    embed_ln_kernel<<<Mn/8, 256>>>(x, emb, ln1g, ln1b);

    dim3 ggridG(Mn/64, 2);
    const size_t CC = (size_t)Cn*Cn;

    for (int i = 0; i < NLn; i++) {
        int d = 1 << i;
        // t = lrelu(ln2( ln1_i(A) @ w1 + b1 ))
        if (i == 0)
            gemm_ln_kernel<4,false,false><<<Mn/64, 256, SMEMLN>>>(
                aP, nullptr, wtP + (i*5+0)*CC, nullptr, b1 + i*Cn,
                ln2g + i*Cn, ln2b + i*Cn, tP, 0,
                nullptr, nullptr, nullptr);
        else
            gemm_ln_kernel<4,false,true><<<Mn/64, 256, SMEMLN>>>(
                nullptr, hP, wtP + (i*5+0)*CC, nullptr, b1 + i*Cn,
                ln2g + i*Cn, ln2b + i*Cn, tP, 0,
                accP, ln1g + i*Cn, ln1b + i*Cn);
        // a = lrelu(ln3(shift(t,d) @ wd0 + t @ wd1 + bd))
        gemm_ln_kernel<8,true,false><<<Mn/64, 256, SMEMLN>>>(
            tP, nullptr, wtP + (i*5+1)*CC, wtP + (i*5+2)*CC, bd + i*Cn,
            ln3g + i*Cn, ln3b + i*Cn, aP, d,
            nullptr, nullptr, nullptr);
        // h += (a@we+be)*sigmoid(a@wg+bg); row partials -> g_acc
        gate_gemm_kernel<<<ggridG, 256, SMEMG>>>(aP, wtP + (i*5+3)*CC, wtP + (i*5+4)*CC,
                                                 be + i*Cn, bg + i*Cn, hP, accP);
    }

    head_kernel<<<Mn/8, 256>>>(x, outW, outb, (float*)d_out);
}